// round 16
// baseline (speedup 1.0000x reference)
#include <cuda_runtime.h>
#include <cuda_fp16.h>
#include <cstdint>

#define D 128
#define T5 5
#define MAXN 100000
#define MAXNP 100096            // padded to 782*128 for GEMM tiles
#define MAXE 1600000
#define NOUT 640                // T*D
#define NBPAD (124 * 4096)      // 507904 (scan coverage, >= 500000 bins)
#define WSZ (NOUT * D)          // 81920 weights per layer
#define EPSV 1e-5f
#define LDH 72                  // half elements per smem row (64 + 8 pad)
#define GEMM_SMEM (2 * 2 * 128 * LDH * 2)   // 73728 bytes (A+B, double buffered, fp16)
#define NSTAT 1184              // colstats block count

// ---------------- device scratch (static; no runtime alloc) ----------------
__device__ __half g_Xh[(size_t)MAXN * D];     // relu(bn(x)) fp16, 25.6 MB (L2-resident)
__device__ __half g_Ah[(size_t)MAXNP * NOUT]; // aggregated activations fp16, ~128 MB
__device__ float g_tmp[(size_t)MAXN * D];     // round-1 output
__device__ __half g_Wh[2 * WSZ];              // fp16 weights (both layers)
__device__ int   g_deg[NBPAD];                // zero-init; hist adds, fill subtracts back to 0
__device__ int   g_local[NBPAD];              // per-4096-block exclusive scan
__device__ int   g_bsum[128];                 // block sums
__device__ int   g_coarse[130];               // coarse exclusive scan
__device__ int   g_srcl[MAXE + 2];            // row BYTE offset (src*256) per edge + 2 pad
__device__ float g_cntf[MAXN * T5];           // edge count per (node,type) as float
__device__ float g_stats[2 * D];              // sum, sumsq (self-resetting)
__device__ float g_ab[2 * D];                 // alpha, beta'
__device__ unsigned int g_ticket_scan;        // self-resetting tickets
__device__ unsigned int g_ticket_cs;
__device__ unsigned int g_ticket_st;

// ---------------- helpers ----------------
__device__ __forceinline__ void cp_async16(void* smem_dst, const void* gmem_src) {
    uint32_t s = (uint32_t)__cvta_generic_to_shared(smem_dst);
    asm volatile("cp.async.cg.shared.global [%0], [%1], 16;\n" :: "r"(s), "l"(gmem_src));
}
#define CP_COMMIT() asm volatile("cp.async.commit_group;\n" ::: "memory")
#define CP_WAIT0()  asm volatile("cp.async.wait_group 0;\n" ::: "memory")

__device__ __forceinline__ void mma_f16(float c[4], const uint32_t a[4], const uint32_t b[2]) {
    asm volatile(
        "mma.sync.aligned.m16n8k16.row.col.f32.f16.f16.f32 "
        "{%0,%1,%2,%3}, {%4,%5,%6,%7}, {%8,%9}, {%0,%1,%2,%3};\n"
        : "+f"(c[0]), "+f"(c[1]), "+f"(c[2]), "+f"(c[3])
        : "r"(a[0]), "r"(a[1]), "r"(a[2]), "r"(a[3]), "r"(b[0]), "r"(b[1]));
}

// ---------------- K0: hist + colstats (independent, merged) ----------------
__global__ void hist_colstats(const int* __restrict__ dst, const int* __restrict__ et, int E,
                              const float* __restrict__ X, const float* __restrict__ g,
                              const float* __restrict__ be, int N, int nbH) {
    int bid = blockIdx.x;
    int tid = threadIdx.x;
    if (bid < nbH) {
        int e = bid * 256 + tid;
        if (e < E) atomicAdd(&g_deg[dst[e] * T5 + et[e]], 1);
        return;
    }
    __shared__ float sred[2 * D];
    __shared__ unsigned int ticket;
    int b = bid - nbH;
    int c4 = tid & 31;
    int rw = tid >> 5;
    float s0 = 0.f, s1 = 0.f, s2v = 0.f, s3 = 0.f;
    float q0 = 0.f, q1 = 0.f, q2 = 0.f, q3 = 0.f;
    for (int r = b * 8 + rw; r < N; r += NSTAT * 8) {
        float4 v = __ldg((const float4*)(X + (size_t)r * D) + c4);
        s0 += v.x; q0 += v.x * v.x;
        s1 += v.y; q1 += v.y * v.y;
        s2v += v.z; q2 += v.z * v.z;
        s3 += v.w; q3 += v.w * v.w;
    }
    if (tid < 256) sred[tid] = 0.f;
    __syncthreads();
    int c0 = c4 * 4;
    atomicAdd(&sred[c0],         s0);
    atomicAdd(&sred[c0 + 1],     s1);
    atomicAdd(&sred[c0 + 2],     s2v);
    atomicAdd(&sred[c0 + 3],     s3);
    atomicAdd(&sred[D + c0],     q0);
    atomicAdd(&sred[D + c0 + 1], q1);
    atomicAdd(&sred[D + c0 + 2], q2);
    atomicAdd(&sred[D + c0 + 3], q3);
    __syncthreads();
    if (tid < 256) atomicAdd(&g_stats[tid], sred[tid]);
    __threadfence();
    if (tid == 0) ticket = atomicInc(&g_ticket_cs, NSTAT - 1);
    __syncthreads();
    if (ticket == NSTAT - 1 && tid < 128) {
        int d = tid;
        float invN = 1.0f / (float)N;
        float su  = atomicAdd(&g_stats[d], 0.f);
        float sq  = atomicAdd(&g_stats[D + d], 0.f);
        float mu  = su * invN;
        float var = sq * invN - mu * mu;
        float a = g[d] * rsqrtf(var + EPSV);
        g_ab[d]     = a;
        g_ab[D + d] = be[d] - a * mu;
        g_stats[d] = 0.f; g_stats[D + d] = 0.f;
    }
}

// ---------------- K1: scan (local + coarse in last block) ----------------
__global__ void scan_kernel(void) {
    __shared__ int ws[32];
    __shared__ unsigned int tk;
    int b = blockIdx.x, tid = threadIdx.x, lane = tid & 31, wid = tid >> 5;
    int4 v = ((const int4*)g_deg)[b * 1024 + tid];
    int s = v.x + v.y + v.z + v.w;
    int x = s;
    #pragma unroll
    for (int o = 1; o < 32; o <<= 1) {
        int y = __shfl_up_sync(0xFFFFFFFFu, x, o);
        if (lane >= o) x += y;
    }
    if (lane == 31) ws[wid] = x;
    __syncthreads();
    if (wid == 0) {
        int w = ws[lane];
        #pragma unroll
        for (int o = 1; o < 32; o <<= 1) {
            int y = __shfl_up_sync(0xFFFFFFFFu, w, o);
            if (lane >= o) w += y;
        }
        ws[lane] = w;
    }
    __syncthreads();
    int excl = (wid ? ws[wid - 1] : 0) + x - s;
    int4 o;
    o.x = excl; o.y = excl + v.x; o.z = o.y + v.y; o.w = o.z + v.z;
    ((int4*)g_local)[b * 1024 + tid] = o;
    if (tid == 1023) g_bsum[b] = excl + s;
    __threadfence();
    if (tid == 0) tk = atomicInc(&g_ticket_scan, gridDim.x - 1);
    __syncthreads();
    if (tk == gridDim.x - 1) {
        int cv = 0, cx = 0;
        if (tid < 128) {
            cv = (tid < 124) ? atomicAdd(&g_bsum[tid], 0) : 0;
            cx = cv;
            #pragma unroll
            for (int of = 1; of < 32; of <<= 1) {
                int y = __shfl_up_sync(0xFFFFFFFFu, cx, of);
                if (lane >= of) cx += y;
            }
            if (lane == 31) ws[wid] = cx;
        }
        __syncthreads();
        if (tid < 128) {
            int woff = 0;
            for (int i = 0; i < wid; i++) woff += ws[i];
            if (tid < 125) g_coarse[tid] = woff + cx - cv;
        }
    }
}

__device__ __forceinline__ int rp_of(int bin) {
    return g_coarse[bin >> 12] + g_local[bin];
}

// ---------------- bnrelu body ----------------
__device__ __forceinline__ void bnrelu_body(const float* __restrict__ X, int i, int nElem4) {
    if (i < nElem4) {
        float4 v = __ldg((const float4*)X + i);
        int d = (i * 4) & 127;
        float4 a = *(const float4*)(g_ab + d);
        float4 b = *(const float4*)(g_ab + D + d);
        float f0 = fmaxf(fmaf(a.x, v.x, b.x), 0.f);
        float f1 = fmaxf(fmaf(a.y, v.y, b.y), 0.f);
        float f2 = fmaxf(fmaf(a.z, v.z, b.z), 0.f);
        float f3 = fmaxf(fmaf(a.w, v.w, b.w), 0.f);
        __half2 h01 = __floats2half2_rn(f0, f1);
        __half2 h23 = __floats2half2_rn(f2, f3);
        uint2 pk;
        pk.x = *(uint32_t*)&h01; pk.y = *(uint32_t*)&h23;
        ((uint2*)g_Xh)[i] = pk;
    }
}

// ---------------- K2: fill_csr + bnrelu(round1) + cvtW (merged) ----------------
__global__ void fill_bnrelu_cvtw(const int* __restrict__ dst, const int* __restrict__ et,
                                 const int* __restrict__ src, int E,
                                 const float* __restrict__ X, int nElem4,
                                 const float* __restrict__ w1, const float* __restrict__ w2,
                                 int nbF, int nbX) {
    int bid = blockIdx.x;
    int tid = threadIdx.x;
    if (bid < nbF) {
        int e = bid * 256 + tid;
        if (e < E) {
            int bin = dst[e] * T5 + et[e];
            int base = rp_of(bin);
            int old = atomicSub(&g_deg[bin], 1);   // deg returns to 0 => self-cleaning
            g_srcl[base + old - 1] = src[e] * 256; // byte offset of row in g_Xh
        }
    } else if (bid < nbF + nbX) {
        bnrelu_body(X, (bid - nbF) * 256 + tid, nElem4);
    } else {
        int i = (bid - nbF - nbX) * 256 + tid;
        if (i < WSZ) {
            g_Wh[i]       = __float2half_rn(w1[i]);
            g_Wh[WSZ + i] = __float2half_rn(w2[i]);
        }
    }
}

// ---------------- round-2 bnrelu ----------------
__global__ void bnrelu_k(const float* __restrict__ X, int nElem4) {
    bnrelu_body(X, blockIdx.x * 256 + threadIdx.x, nElem4);
}

// ---------------- aggregate: warp per node, HADD2 accumulation (R14, unchanged) ----------------
__global__ void aggregate(int N) {
    int w = (blockIdx.x * blockDim.x + threadIdx.x) >> 5;
    int lane = threadIdx.x & 31;
    if (w >= N) return;
    int bin0 = w * T5;
    int rpv[6];
    #pragma unroll
    for (int i = 0; i < 6; i++) rpv[i] = rp_of(bin0 + i);

    const char* base = (const char*)g_Xh + lane * 8;
    int e = rpv[0];
    int off = __ldg(&g_srcl[e]);

    const __half2 hz = __float2half2_rn(0.f);
    __half* Arow = g_Ah + (size_t)w * NOUT;
    #pragma unroll
    for (int t = 0; t < T5; t++) {
        int end = rpv[t + 1];
        int cnt = end - rpv[t];
        __half2 aA = hz, aB = hz, bA = hz, bB = hz;
        while (e + 1 < end) {
            int off1 = __ldg(&g_srcl[e + 1]);
            int off2 = __ldg(&g_srcl[e + 2]);
            uint2 v0 = __ldg((const uint2*)(base + off));
            uint2 v1 = __ldg((const uint2*)(base + off1));
            aA = __hadd2(aA, *(__half2*)&v0.x);
            aB = __hadd2(aB, *(__half2*)&v0.y);
            bA = __hadd2(bA, *(__half2*)&v1.x);
            bB = __hadd2(bB, *(__half2*)&v1.y);
            off = off2;
            e += 2;
        }
        if (e < end) {
            int off1 = __ldg(&g_srcl[e + 1]);
            uint2 v0 = __ldg((const uint2*)(base + off));
            aA = __hadd2(aA, *(__half2*)&v0.x);
            aB = __hadd2(aB, *(__half2*)&v0.y);
            off = off1;
            e++;
        }
        float2 fa0 = __half22float2(aA), fb0 = __half22float2(bA);
        float2 fa1 = __half22float2(aB), fb1 = __half22float2(bB);
        __half2 h01 = __floats2half2_rn(fa0.x + fb0.x, fa0.y + fb0.y);
        __half2 h23 = __floats2half2_rn(fa1.x + fb1.x, fa1.y + fb1.y);
        uint2 pk;
        pk.x = *(uint32_t*)&h01; pk.y = *(uint32_t*)&h23;
        *(uint2*)(Arow + t * D + 4 * lane) = pk;
        if (lane == 0) g_cntf[bin0 + t] = (float)cnt;
    }
}

// ---------------- tall fp16 GEMM: 128x128 tile, 4 warps, 64x64 warp tiles ----------------
// Fragment reuse: each A frag feeds 8 n-tiles, each B frag feeds 4 m-tiles
// -> per-chunk LDS drops 768 -> 512 per CTA vs 32x32 warp tiles.
__global__ void __launch_bounds__(128, 2) gemm_agg(
    const __half* __restrict__ W, const float* __restrict__ bias,
    const float* __restrict__ addend, float* __restrict__ out, int Nrows,
    const float* __restrict__ gamma, const float* __restrict__ beta) {
    extern __shared__ __half smh[];
    int tid = threadIdx.x;
    int row0 = blockIdx.x * 128;
    const __half* Agl = g_Ah + (size_t)row0 * NOUT;

    int warp = tid >> 5, lane = tid & 31;
    int wm = warp >> 1, wn = warp & 1;           // 2x2 warps, warp tile 64x64
    int wrow = wm * 64, wcol = wn * 64;
    int gid = lane >> 2, tig = lane & 3;

    float c[4][8][4];
    #pragma unroll
    for (int mt = 0; mt < 4; mt++)
        #pragma unroll
        for (int nt = 0; nt < 8; nt++)
            #pragma unroll
            for (int q = 0; q < 4; q++) c[mt][nt][q] = 0.f;

    const int NC = NOUT / 64;  // 10 chunks of K=64

    auto load_chunk = [&](int cidx, int buf) {
        int k0 = cidx * 64;
        int t = k0 >> 7, kd = k0 & 127;
        __half* as = smh + buf * (2 * 128 * LDH);
        __half* bs = as + 128 * LDH;
        const __half* Asrc = Agl + k0;
        const __half* Bsrc = W + ((size_t)t * 128) * 128 + kd;
        #pragma unroll
        for (int i = 0; i < 8; i++) {
            int gnum = tid + i * 128;
            int r = gnum >> 3, sg = gnum & 7;
            cp_async16(as + r * LDH + sg * 8, Asrc + (size_t)r * NOUT + sg * 8);
        }
        #pragma unroll
        for (int i = 0; i < 8; i++) {
            int gnum = tid + i * 128;
            int j = gnum >> 3, sg = gnum & 7;
            cp_async16(bs + j * LDH + sg * 8, Bsrc + (size_t)j * 128 + sg * 8);
        }
        CP_COMMIT();
    };

    load_chunk(0, 0);
    for (int cidx = 0; cidx < NC; cidx++) {
        CP_WAIT0();
        __syncthreads();
        if (cidx + 1 < NC) load_chunk(cidx + 1, (cidx + 1) & 1);
        const __half* as = smh + (cidx & 1) * (2 * 128 * LDH);
        const __half* bs = as + 128 * LDH;
        #pragma unroll
        for (int ks = 0; ks < 4; ks++) {
            int kk = ks * 16;
            uint32_t a[4][4], b[8][2];
            #pragma unroll
            for (int mt = 0; mt < 4; mt++) {
                int r = wrow + mt * 16 + gid;
                a[mt][0] = *(const uint32_t*)(as + r * LDH + kk + tig * 2);
                a[mt][1] = *(const uint32_t*)(as + (r + 8) * LDH + kk + tig * 2);
                a[mt][2] = *(const uint32_t*)(as + r * LDH + kk + tig * 2 + 8);
                a[mt][3] = *(const uint32_t*)(as + (r + 8) * LDH + kk + tig * 2 + 8);
            }
            #pragma unroll
            for (int nt = 0; nt < 8; nt++) {
                int j = wcol + nt * 8 + gid;
                b[nt][0] = *(const uint32_t*)(bs + j * LDH + kk + tig * 2);
                b[nt][1] = *(const uint32_t*)(bs + j * LDH + kk + tig * 2 + 8);
            }
            #pragma unroll
            for (int mt = 0; mt < 4; mt++)
                #pragma unroll
                for (int nt = 0; nt < 8; nt++)
                    mma_f16(c[mt][nt], a[mt], b[nt]);
        }
        __syncthreads();
    }

    // epilogue: per-(node,type) count x bias + optional residual + optional fused stats
    float* smf  = (float*)smh;
    float* cntS = smf;          // [128][5]
    float* bsm  = smf + 640;    // [5][128]
    float* ssum = smf + 1280;   // [128]
    float* ssq  = smf + 1408;   // [128]
    for (int i = tid; i < 640; i += 128) {
        int r = i / T5, t = i % T5;
        int gr = row0 + r;
        cntS[i] = (gr < Nrows) ? g_cntf[gr * T5 + t] : 0.f;
        bsm[i] = __ldg(&bias[i]);
    }
    if (tid < 128) { ssum[tid] = 0.f; ssq[tid] = 0.f; }
    __syncthreads();

    float ps[16], pq[16];
    #pragma unroll
    for (int q = 0; q < 16; q++) { ps[q] = 0.f; pq[q] = 0.f; }

    #pragma unroll
    for (int mt = 0; mt < 4; mt++) {
        #pragma unroll
        for (int half = 0; half < 2; half++) {
            int r = wrow + mt * 16 + gid + half * 8;   // 0..127
            int grow = row0 + r;
            if (grow >= Nrows) continue;
            #pragma unroll
            for (int nt = 0; nt < 8; nt++) {
                int j = wcol + nt * 8 + 2 * tig;
                float b0 = 0.f, b1 = 0.f;
                #pragma unroll
                for (int t = 0; t < T5; t++) {
                    float cn = cntS[r * T5 + t];
                    b0 = fmaf(cn, bsm[t * 128 + j], b0);
                    b1 = fmaf(cn, bsm[t * 128 + j + 1], b1);
                }
                float v0 = c[mt][nt][half * 2]     + b0;
                float v1 = c[mt][nt][half * 2 + 1] + b1;
                if (gamma) {
                    ps[nt * 2]     += v0; pq[nt * 2]     += v0 * v0;
                    ps[nt * 2 + 1] += v1; pq[nt * 2 + 1] += v1 * v1;
                }
                if (addend) {
                    float2 ad = *(const float2*)(addend + (size_t)grow * D + j);
                    v0 += ad.x; v1 += ad.y;
                }
                *(float2*)(out + (size_t)grow * D + j) = make_float2(v0, v1);
            }
        }
    }

    if (gamma) {
        #pragma unroll
        for (int nt = 0; nt < 8; nt++) {
            int j = wcol + nt * 8 + 2 * tig;
            atomicAdd(&ssum[j],     ps[nt * 2]);
            atomicAdd(&ssum[j + 1], ps[nt * 2 + 1]);
            atomicAdd(&ssq[j],      pq[nt * 2]);
            atomicAdd(&ssq[j + 1],  pq[nt * 2 + 1]);
        }
        __syncthreads();
        if (tid < 128) {
            atomicAdd(&g_stats[tid],     ssum[tid]);
            atomicAdd(&g_stats[D + tid], ssq[tid]);
        }
        __threadfence();
        __shared__ unsigned int ticket;
        if (tid == 0) ticket = atomicInc(&g_ticket_st, gridDim.x - 1);
        __syncthreads();
        if (ticket == gridDim.x - 1 && tid < 128) {
            int d = tid;
            float invN = 1.0f / (float)Nrows;
            float su  = atomicAdd(&g_stats[d], 0.f);
            float sq  = atomicAdd(&g_stats[D + d], 0.f);
            float mu  = su * invN;
            float var = sq * invN - mu * mu;
            float a = gamma[d] * rsqrtf(var + EPSV);
            g_ab[d]     = a;
            g_ab[D + d] = beta[d] - a * mu;
            g_stats[d] = 0.f; g_stats[D + d] = 0.f;
        }
    }
}

// ---------------- launch ----------------
extern "C" void kernel_launch(void* const* d_in, const int* in_sizes, int n_in,
                              void* d_out, int out_size) {
    const float* features = (const float*)d_in[0];
    const int*   src      = (const int*)d_in[1];
    const int*   dst      = (const int*)d_in[2];
    const int*   etype    = (const int*)d_in[3];
    const float* w1       = (const float*)d_in[4];
    const float* b1       = (const float*)d_in[5];
    const float* g1       = (const float*)d_in[6];
    const float* be1      = (const float*)d_in[7];
    const float* w2       = (const float*)d_in[8];
    const float* b2       = (const float*)d_in[9];
    const float* g2       = (const float*)d_in[10];
    const float* be2      = (const float*)d_in[11];

    int N = in_sizes[0] / D;
    int E = in_sizes[1];

    float* tmp;
    __half* Wh;
    cudaGetSymbolAddress((void**)&tmp, g_tmp);
    cudaGetSymbolAddress((void**)&Wh, g_Wh);

    cudaFuncSetAttribute(gemm_agg, cudaFuncAttributeMaxDynamicSharedMemorySize, GEMM_SMEM);

    int nElem4 = (N * D) / 4;
    int nbX = (nElem4 + 255) / 256;
    int nbW = (WSZ + 255) / 256;
    int nbH = (E + 255) / 256;
    int gemm_blocks = (N + 127) / 128;
    int agg_blocks  = (N * 32 + 255) / 256;

    hist_colstats<<<nbH + NSTAT, 256>>>(dst, etype, E, features, g1, be1, N, nbH);   // 0
    scan_kernel<<<124, 1024>>>();                                                    // 1
    fill_bnrelu_cvtw<<<nbH + nbX + nbW, 256>>>(dst, etype, src, E,
                                               features, nElem4, w1, w2, nbH, nbX);  // 2
    aggregate<<<agg_blocks, 256>>>(N);                                               // 3
    gemm_agg<<<gemm_blocks, 128, GEMM_SMEM>>>(Wh, b1, nullptr, tmp, N, g2, be2);     // 4 (stats fused)
    bnrelu_k<<<nbX, 256>>>(tmp, nElem4);                                             // 5
    aggregate<<<agg_blocks, 256>>>(N);                                               // 6
    gemm_agg<<<gemm_blocks, 128, GEMM_SMEM>>>(Wh + WSZ, b2, features, (float*)d_out, N,
                                              nullptr, nullptr);                     // 7
}

// round 17
// speedup vs baseline: 1.0250x; 1.0250x over previous
#include <cuda_runtime.h>
#include <cuda_fp16.h>
#include <cstdint>

#define D 128
#define T5 5
#define MAXN 100000
#define MAXNP 100096            // padded to 782*128 for GEMM tiles
#define MAXE 1600000
#define NOUT 640                // T*D
#define NBPAD (124 * 4096)      // 507904 (scan coverage, >= 500000 bins)
#define WSZ (NOUT * D)          // 81920 weights per layer
#define EPSV 1e-5f
#define LDH 72                  // half elements per smem row (64 + 8 pad)
#define STAGE_HALVES (2 * 128 * LDH)        // A+B per stage (18432 halves = 36864 B)
#define GEMM_SMEM (3 * STAGE_HALVES * 2)    // 110592 bytes, 3-stage ring
#define NSTAT 1184              // colstats block count

// ---------------- device scratch (static; no runtime alloc) ----------------
__device__ __half g_Xh[(size_t)MAXN * D];     // relu(bn(x)) fp16, 25.6 MB (L2-resident)
__device__ __half g_Ah[(size_t)MAXNP * NOUT]; // aggregated activations fp16, ~128 MB
__device__ float g_tmp[(size_t)MAXN * D];     // round-1 output
__device__ __half g_Wh[2 * WSZ];              // fp16 weights (both layers)
__device__ int   g_deg[NBPAD];                // zero-init; hist adds, fill subtracts back to 0
__device__ int   g_local[NBPAD];              // per-4096-block exclusive scan
__device__ int   g_bsum[128];                 // block sums
__device__ int   g_coarse[130];               // coarse exclusive scan
__device__ int   g_srcl[MAXE + 2];            // row BYTE offset (src*256) per edge + 2 pad
__device__ float g_cntf[MAXN * T5];           // edge count per (node,type) as float
__device__ float g_stats[2 * D];              // sum, sumsq (self-resetting)
__device__ float g_ab[2 * D];                 // alpha, beta'
__device__ unsigned int g_ticket_scan;        // self-resetting tickets
__device__ unsigned int g_ticket_cs;
__device__ unsigned int g_ticket_st;

// ---------------- helpers ----------------
__device__ __forceinline__ void cp_async16(void* smem_dst, const void* gmem_src) {
    uint32_t s = (uint32_t)__cvta_generic_to_shared(smem_dst);
    asm volatile("cp.async.cg.shared.global [%0], [%1], 16;\n" :: "r"(s), "l"(gmem_src));
}
#define CP_COMMIT() asm volatile("cp.async.commit_group;\n" ::: "memory")
#define CP_WAIT0()  asm volatile("cp.async.wait_group 0;\n" ::: "memory")
#define CP_WAIT1()  asm volatile("cp.async.wait_group 1;\n" ::: "memory")

__device__ __forceinline__ void mma_f16(float c[4], const uint32_t a[4], const uint32_t b[2]) {
    asm volatile(
        "mma.sync.aligned.m16n8k16.row.col.f32.f16.f16.f32 "
        "{%0,%1,%2,%3}, {%4,%5,%6,%7}, {%8,%9}, {%0,%1,%2,%3};\n"
        : "+f"(c[0]), "+f"(c[1]), "+f"(c[2]), "+f"(c[3])
        : "r"(a[0]), "r"(a[1]), "r"(a[2]), "r"(a[3]), "r"(b[0]), "r"(b[1]));
}

// ---------------- K0: hist + colstats (independent, merged) ----------------
__global__ void hist_colstats(const int* __restrict__ dst, const int* __restrict__ et, int E,
                              const float* __restrict__ X, const float* __restrict__ g,
                              const float* __restrict__ be, int N, int nbH) {
    int bid = blockIdx.x;
    int tid = threadIdx.x;
    if (bid < nbH) {
        int e = bid * 256 + tid;
        if (e < E) atomicAdd(&g_deg[dst[e] * T5 + et[e]], 1);
        return;
    }
    __shared__ float sred[2 * D];
    __shared__ unsigned int ticket;
    int b = bid - nbH;
    int c4 = tid & 31;
    int rw = tid >> 5;
    float s0 = 0.f, s1 = 0.f, s2v = 0.f, s3 = 0.f;
    float q0 = 0.f, q1 = 0.f, q2 = 0.f, q3 = 0.f;
    for (int r = b * 8 + rw; r < N; r += NSTAT * 8) {
        float4 v = __ldg((const float4*)(X + (size_t)r * D) + c4);
        s0 += v.x; q0 += v.x * v.x;
        s1 += v.y; q1 += v.y * v.y;
        s2v += v.z; q2 += v.z * v.z;
        s3 += v.w; q3 += v.w * v.w;
    }
    if (tid < 256) sred[tid] = 0.f;
    __syncthreads();
    int c0 = c4 * 4;
    atomicAdd(&sred[c0],         s0);
    atomicAdd(&sred[c0 + 1],     s1);
    atomicAdd(&sred[c0 + 2],     s2v);
    atomicAdd(&sred[c0 + 3],     s3);
    atomicAdd(&sred[D + c0],     q0);
    atomicAdd(&sred[D + c0 + 1], q1);
    atomicAdd(&sred[D + c0 + 2], q2);
    atomicAdd(&sred[D + c0 + 3], q3);
    __syncthreads();
    if (tid < 256) atomicAdd(&g_stats[tid], sred[tid]);
    __threadfence();
    if (tid == 0) ticket = atomicInc(&g_ticket_cs, NSTAT - 1);
    __syncthreads();
    if (ticket == NSTAT - 1 && tid < 128) {
        int d = tid;
        float invN = 1.0f / (float)N;
        float su  = atomicAdd(&g_stats[d], 0.f);
        float sq  = atomicAdd(&g_stats[D + d], 0.f);
        float mu  = su * invN;
        float var = sq * invN - mu * mu;
        float a = g[d] * rsqrtf(var + EPSV);
        g_ab[d]     = a;
        g_ab[D + d] = be[d] - a * mu;
        g_stats[d] = 0.f; g_stats[D + d] = 0.f;
    }
}

// ---------------- K1: scan (local + coarse in last block) ----------------
__global__ void scan_kernel(void) {
    __shared__ int ws[32];
    __shared__ unsigned int tk;
    int b = blockIdx.x, tid = threadIdx.x, lane = tid & 31, wid = tid >> 5;
    int4 v = ((const int4*)g_deg)[b * 1024 + tid];
    int s = v.x + v.y + v.z + v.w;
    int x = s;
    #pragma unroll
    for (int o = 1; o < 32; o <<= 1) {
        int y = __shfl_up_sync(0xFFFFFFFFu, x, o);
        if (lane >= o) x += y;
    }
    if (lane == 31) ws[wid] = x;
    __syncthreads();
    if (wid == 0) {
        int w = ws[lane];
        #pragma unroll
        for (int o = 1; o < 32; o <<= 1) {
            int y = __shfl_up_sync(0xFFFFFFFFu, w, o);
            if (lane >= o) w += y;
        }
        ws[lane] = w;
    }
    __syncthreads();
    int excl = (wid ? ws[wid - 1] : 0) + x - s;
    int4 o;
    o.x = excl; o.y = excl + v.x; o.z = o.y + v.y; o.w = o.z + v.z;
    ((int4*)g_local)[b * 1024 + tid] = o;
    if (tid == 1023) g_bsum[b] = excl + s;
    __threadfence();
    if (tid == 0) tk = atomicInc(&g_ticket_scan, gridDim.x - 1);
    __syncthreads();
    if (tk == gridDim.x - 1) {
        int cv = 0, cx = 0;
        if (tid < 128) {
            cv = (tid < 124) ? atomicAdd(&g_bsum[tid], 0) : 0;
            cx = cv;
            #pragma unroll
            for (int of = 1; of < 32; of <<= 1) {
                int y = __shfl_up_sync(0xFFFFFFFFu, cx, of);
                if (lane >= of) cx += y;
            }
            if (lane == 31) ws[wid] = cx;
        }
        __syncthreads();
        if (tid < 128) {
            int woff = 0;
            for (int i = 0; i < wid; i++) woff += ws[i];
            if (tid < 125) g_coarse[tid] = woff + cx - cv;
        }
    }
}

__device__ __forceinline__ int rp_of(int bin) {
    return g_coarse[bin >> 12] + g_local[bin];
}

// ---------------- bnrelu body ----------------
__device__ __forceinline__ void bnrelu_body(const float* __restrict__ X, int i, int nElem4) {
    if (i < nElem4) {
        float4 v = __ldg((const float4*)X + i);
        int d = (i * 4) & 127;
        float4 a = *(const float4*)(g_ab + d);
        float4 b = *(const float4*)(g_ab + D + d);
        float f0 = fmaxf(fmaf(a.x, v.x, b.x), 0.f);
        float f1 = fmaxf(fmaf(a.y, v.y, b.y), 0.f);
        float f2 = fmaxf(fmaf(a.z, v.z, b.z), 0.f);
        float f3 = fmaxf(fmaf(a.w, v.w, b.w), 0.f);
        __half2 h01 = __floats2half2_rn(f0, f1);
        __half2 h23 = __floats2half2_rn(f2, f3);
        uint2 pk;
        pk.x = *(uint32_t*)&h01; pk.y = *(uint32_t*)&h23;
        ((uint2*)g_Xh)[i] = pk;
    }
}

// ---------------- K2: fill_csr + bnrelu(round1) + cvtW (merged) ----------------
__global__ void fill_bnrelu_cvtw(const int* __restrict__ dst, const int* __restrict__ et,
                                 const int* __restrict__ src, int E,
                                 const float* __restrict__ X, int nElem4,
                                 const float* __restrict__ w1, const float* __restrict__ w2,
                                 int nbF, int nbX) {
    int bid = blockIdx.x;
    int tid = threadIdx.x;
    if (bid < nbF) {
        int e = bid * 256 + tid;
        if (e < E) {
            int bin = dst[e] * T5 + et[e];
            int base = rp_of(bin);
            int old = atomicSub(&g_deg[bin], 1);   // deg returns to 0 => self-cleaning
            g_srcl[base + old - 1] = src[e] * 256; // byte offset of row in g_Xh
        }
    } else if (bid < nbF + nbX) {
        bnrelu_body(X, (bid - nbF) * 256 + tid, nElem4);
    } else {
        int i = (bid - nbF - nbX) * 256 + tid;
        if (i < WSZ) {
            g_Wh[i]       = __float2half_rn(w1[i]);
            g_Wh[WSZ + i] = __float2half_rn(w2[i]);
        }
    }
}

// ---------------- round-2 bnrelu ----------------
__global__ void bnrelu_k(const float* __restrict__ X, int nElem4) {
    bnrelu_body(X, blockIdx.x * 256 + threadIdx.x, nElem4);
}

// ---------------- aggregate: warp per node, HADD2 accumulation (R14, unchanged) ----------------
__global__ void aggregate(int N) {
    int w = (blockIdx.x * blockDim.x + threadIdx.x) >> 5;
    int lane = threadIdx.x & 31;
    if (w >= N) return;
    int bin0 = w * T5;
    int rpv[6];
    #pragma unroll
    for (int i = 0; i < 6; i++) rpv[i] = rp_of(bin0 + i);

    const char* base = (const char*)g_Xh + lane * 8;
    int e = rpv[0];
    int off = __ldg(&g_srcl[e]);

    const __half2 hz = __float2half2_rn(0.f);
    __half* Arow = g_Ah + (size_t)w * NOUT;
    #pragma unroll
    for (int t = 0; t < T5; t++) {
        int end = rpv[t + 1];
        int cnt = end - rpv[t];
        __half2 aA = hz, aB = hz, bA = hz, bB = hz;
        while (e + 1 < end) {
            int off1 = __ldg(&g_srcl[e + 1]);
            int off2 = __ldg(&g_srcl[e + 2]);
            uint2 v0 = __ldg((const uint2*)(base + off));
            uint2 v1 = __ldg((const uint2*)(base + off1));
            aA = __hadd2(aA, *(__half2*)&v0.x);
            aB = __hadd2(aB, *(__half2*)&v0.y);
            bA = __hadd2(bA, *(__half2*)&v1.x);
            bB = __hadd2(bB, *(__half2*)&v1.y);
            off = off2;
            e += 2;
        }
        if (e < end) {
            int off1 = __ldg(&g_srcl[e + 1]);
            uint2 v0 = __ldg((const uint2*)(base + off));
            aA = __hadd2(aA, *(__half2*)&v0.x);
            aB = __hadd2(aB, *(__half2*)&v0.y);
            off = off1;
            e++;
        }
        float2 fa0 = __half22float2(aA), fb0 = __half22float2(bA);
        float2 fa1 = __half22float2(aB), fb1 = __half22float2(bB);
        __half2 h01 = __floats2half2_rn(fa0.x + fb0.x, fa0.y + fb0.y);
        __half2 h23 = __floats2half2_rn(fa1.x + fb1.x, fa1.y + fb1.y);
        uint2 pk;
        pk.x = *(uint32_t*)&h01; pk.y = *(uint32_t*)&h23;
        *(uint2*)(Arow + t * D + 4 * lane) = pk;
        if (lane == 0) g_cntf[bin0 + t] = (float)cnt;
    }
}

// ---------------- tall fp16 GEMM: 128x128 tile, K=640, 3-stage cp.async pipeline ----------------
// R14 shape (256 threads, 2x4 warps, 32x32 warp tiles); only the pipeline is deeper.
__global__ void __launch_bounds__(256, 2) gemm_agg(
    const __half* __restrict__ W, const float* __restrict__ bias,
    const float* __restrict__ addend, float* __restrict__ out, int Nrows,
    const float* __restrict__ gamma, const float* __restrict__ beta) {
    extern __shared__ __half smh[];
    int tid = threadIdx.x;
    int row0 = blockIdx.x * 128;
    const __half* Agl = g_Ah + (size_t)row0 * NOUT;

    int warp = tid >> 5, lane = tid & 31;
    int wm = warp >> 2, wn = warp & 3;           // 2x4 warps, warp tile 64x32
    int wrow = wm * 64, wcol = wn * 32;
    int gid = lane >> 2, tig = lane & 3;

    float c[4][4][4];
    #pragma unroll
    for (int mt = 0; mt < 4; mt++)
        #pragma unroll
        for (int nt = 0; nt < 4; nt++)
            #pragma unroll
            for (int q = 0; q < 4; q++) c[mt][nt][q] = 0.f;

    const int NC = NOUT / 64;  // 10 chunks of K=64

    auto load_chunk = [&](int cidx, int buf) {
        int k0 = cidx * 64;
        int t = k0 >> 7, kd = k0 & 127;
        __half* as = smh + buf * STAGE_HALVES;
        __half* bs = as + 128 * LDH;
        const __half* Asrc = Agl + k0;
        const __half* Bsrc = W + ((size_t)t * 128) * 128 + kd;
        #pragma unroll
        for (int i = 0; i < 4; i++) {
            int gnum = tid + i * 256;
            int r = gnum >> 3, sg = gnum & 7;
            cp_async16(as + r * LDH + sg * 8, Asrc + (size_t)r * NOUT + sg * 8);
        }
        #pragma unroll
        for (int i = 0; i < 4; i++) {
            int gnum = tid + i * 256;
            int j = gnum >> 3, sg = gnum & 7;
            cp_async16(bs + j * LDH + sg * 8, Bsrc + (size_t)j * 128 + sg * 8);
        }
        CP_COMMIT();
    };

    load_chunk(0, 0);
    load_chunk(1, 1);
    int buf = 0, nbuf3 = 2;   // buffer of chunk c; buffer for chunk c+2
    for (int cidx = 0; cidx < NC; cidx++) {
        if (cidx < NC - 1) { CP_WAIT1(); } else { CP_WAIT0(); }
        __syncthreads();     // chunk cidx ready; compute(cidx-1) done by all warps
        if (cidx + 2 < NC) load_chunk(cidx + 2, nbuf3);  // overwrites buffer of compute(cidx-1)
        const __half* as = smh + buf * STAGE_HALVES;
        const __half* bs = as + 128 * LDH;
        #pragma unroll
        for (int ks = 0; ks < 4; ks++) {
            int kk = ks * 16;
            uint32_t a[4][4], b[4][2];
            #pragma unroll
            for (int mt = 0; mt < 4; mt++) {
                int r = wrow + mt * 16 + gid;
                a[mt][0] = *(const uint32_t*)(as + r * LDH + kk + tig * 2);
                a[mt][1] = *(const uint32_t*)(as + (r + 8) * LDH + kk + tig * 2);
                a[mt][2] = *(const uint32_t*)(as + r * LDH + kk + tig * 2 + 8);
                a[mt][3] = *(const uint32_t*)(as + (r + 8) * LDH + kk + tig * 2 + 8);
            }
            #pragma unroll
            for (int nt = 0; nt < 4; nt++) {
                int j = wcol + nt * 8 + gid;
                b[nt][0] = *(const uint32_t*)(bs + j * LDH + kk + tig * 2);
                b[nt][1] = *(const uint32_t*)(bs + j * LDH + kk + tig * 2 + 8);
            }
            #pragma unroll
            for (int mt = 0; mt < 4; mt++)
                #pragma unroll
                for (int nt = 0; nt < 4; nt++)
                    mma_f16(c[mt][nt], a[mt], b[nt]);
        }
        buf = (buf == 2) ? 0 : buf + 1;
        nbuf3 = (nbuf3 == 2) ? 0 : nbuf3 + 1;
    }
    __syncthreads();   // all compute done before epilogue reuses stage-0 smem

    // epilogue: per-(node,type) count x bias + optional residual + optional fused stats
    float* smf  = (float*)smh;
    float* cntS = smf;          // [128][5]
    float* bsm  = smf + 640;    // [5][128]
    float* ssum = smf + 1280;   // [128]
    float* ssq  = smf + 1408;   // [128]
    for (int i = tid; i < 640; i += 256) {
        int r = i / T5, t = i % T5;
        int gr = row0 + r;
        cntS[i] = (gr < Nrows) ? g_cntf[gr * T5 + t] : 0.f;
        bsm[i] = __ldg(&bias[i]);
    }
    if (tid < 128) { ssum[tid] = 0.f; ssq[tid] = 0.f; }
    __syncthreads();

    float ps[8], pq[8];
    #pragma unroll
    for (int q = 0; q < 8; q++) { ps[q] = 0.f; pq[q] = 0.f; }

    #pragma unroll
    for (int mt = 0; mt < 4; mt++) {
        #pragma unroll
        for (int half = 0; half < 2; half++) {
            int r = wrow + mt * 16 + gid + half * 8;   // 0..127
            int grow = row0 + r;
            if (grow >= Nrows) continue;
            #pragma unroll
            for (int nt = 0; nt < 4; nt++) {
                int j = wcol + nt * 8 + 2 * tig;
                float b0 = 0.f, b1 = 0.f;
                #pragma unroll
                for (int t = 0; t < T5; t++) {
                    float cn = cntS[r * T5 + t];
                    b0 = fmaf(cn, bsm[t * 128 + j], b0);
                    b1 = fmaf(cn, bsm[t * 128 + j + 1], b1);
                }
                float v0 = c[mt][nt][half * 2]     + b0;
                float v1 = c[mt][nt][half * 2 + 1] + b1;
                if (gamma) {
                    ps[nt * 2]     += v0; pq[nt * 2]     += v0 * v0;
                    ps[nt * 2 + 1] += v1; pq[nt * 2 + 1] += v1 * v1;
                }
                if (addend) {
                    float2 ad = *(const float2*)(addend + (size_t)grow * D + j);
                    v0 += ad.x; v1 += ad.y;
                }
                *(float2*)(out + (size_t)grow * D + j) = make_float2(v0, v1);
            }
        }
    }

    if (gamma) {
        #pragma unroll
        for (int nt = 0; nt < 4; nt++) {
            int j = wcol + nt * 8 + 2 * tig;
            atomicAdd(&ssum[j],     ps[nt * 2]);
            atomicAdd(&ssum[j + 1], ps[nt * 2 + 1]);
            atomicAdd(&ssq[j],      pq[nt * 2]);
            atomicAdd(&ssq[j + 1],  pq[nt * 2 + 1]);
        }
        __syncthreads();
        if (tid < 128) {
            atomicAdd(&g_stats[tid],     ssum[tid]);
            atomicAdd(&g_stats[D + tid], ssq[tid]);
        }
        __threadfence();
        __shared__ unsigned int ticket;
        if (tid == 0) ticket = atomicInc(&g_ticket_st, gridDim.x - 1);
        __syncthreads();
        if (ticket == gridDim.x - 1 && tid < 128) {
            int d = tid;
            float invN = 1.0f / (float)Nrows;
            float su  = atomicAdd(&g_stats[d], 0.f);
            float sq  = atomicAdd(&g_stats[D + d], 0.f);
            float mu  = su * invN;
            float var = sq * invN - mu * mu;
            float a = gamma[d] * rsqrtf(var + EPSV);
            g_ab[d]     = a;
            g_ab[D + d] = beta[d] - a * mu;
            g_stats[d] = 0.f; g_stats[D + d] = 0.f;
        }
    }
}

// ---------------- launch ----------------
extern "C" void kernel_launch(void* const* d_in, const int* in_sizes, int n_in,
                              void* d_out, int out_size) {
    const float* features = (const float*)d_in[0];
    const int*   src      = (const int*)d_in[1];
    const int*   dst      = (const int*)d_in[2];
    const int*   etype    = (const int*)d_in[3];
    const float* w1       = (const float*)d_in[4];
    const float* b1       = (const float*)d_in[5];
    const float* g1       = (const float*)d_in[6];
    const float* be1      = (const float*)d_in[7];
    const float* w2       = (const float*)d_in[8];
    const float* b2       = (const float*)d_in[9];
    const float* g2       = (const float*)d_in[10];
    const float* be2      = (const float*)d_in[11];

    int N = in_sizes[0] / D;
    int E = in_sizes[1];

    float* tmp;
    __half* Wh;
    cudaGetSymbolAddress((void**)&tmp, g_tmp);
    cudaGetSymbolAddress((void**)&Wh, g_Wh);

    cudaFuncSetAttribute(gemm_agg, cudaFuncAttributeMaxDynamicSharedMemorySize, GEMM_SMEM);

    int nElem4 = (N * D) / 4;
    int nbX = (nElem4 + 255) / 256;
    int nbW = (WSZ + 255) / 256;
    int nbH = (E + 255) / 256;
    int gemm_blocks = (N + 127) / 128;
    int agg_blocks  = (N * 32 + 255) / 256;

    hist_colstats<<<nbH + NSTAT, 256>>>(dst, etype, E, features, g1, be1, N, nbH);   // 0
    scan_kernel<<<124, 1024>>>();                                                    // 1
    fill_bnrelu_cvtw<<<nbH + nbX + nbW, 256>>>(dst, etype, src, E,
                                               features, nElem4, w1, w2, nbH, nbX);  // 2
    aggregate<<<agg_blocks, 256>>>(N);                                               // 3
    gemm_agg<<<gemm_blocks, 256, GEMM_SMEM>>>(Wh, b1, nullptr, tmp, N, g2, be2);     // 4 (stats fused)
    bnrelu_k<<<nbX, 256>>>(tmp, nElem4);                                             // 5
    aggregate<<<agg_blocks, 256>>>(N);                                               // 6
    gemm_agg<<<gemm_blocks, 256, GEMM_SMEM>>>(Wh + WSZ, b2, features, (float*)d_out, N,
                                              nullptr, nullptr);                     // 7
}